// round 4
// baseline (speedup 1.0000x reference)
#include <cuda_runtime.h>
#include <math.h>

// ---------------------------------------------------------------------------
// CompressedSensingInception on GB300, round 4.
//   k_main  : grid 128. Blocks 0..95: one (b,c) FISTA each, f32x2-packed math.
//             Blocks 96..127: w-channel + y branch + yc.
//   k_c51/k_c15 : conv stages, float4 over output channels.
//   k_c55x2 : c55 conv (float4 weights+src, 4 acc) fused with x2 epilogue.
// ---------------------------------------------------------------------------

#define BNS 0.9995003746877732f   // 1/sqrt(1+1e-3)

typedef unsigned long long u64;

static __device__ __forceinline__ float leakyf(float v) { return v >= 0.f ? v : 0.3f * v; }
static __device__ __forceinline__ u64 pk2(float lo, float hi) {
    u64 r; asm("mov.b64 %0, {%1, %2};" : "=l"(r) : "f"(lo), "f"(hi)); return r;
}
static __device__ __forceinline__ void upk2(u64 v, float& lo, float& hi) {
    asm("mov.b64 {%0, %1}, %2;" : "=f"(lo), "=f"(hi) : "l"(v));
}
static __device__ __forceinline__ u64 ffma2(u64 a, u64 b, u64 c) {
    u64 d; asm("fma.rn.f32x2 %0, %1, %2, %3;" : "=l"(d) : "l"(a), "l"(b), "l"(c)); return d;
}
static __device__ __forceinline__ u64 fadd2(u64 a, u64 b) {
    u64 d; asm("add.rn.f32x2 %0, %1, %2;" : "=l"(d) : "l"(a), "l"(b)); return d;
}

__device__ __align__(16) float g_cs[32 * 5184 * 3];  // (B,72,72,3)
__device__ __align__(16) float g_t1[32 * 36 * 36 * 16];
__device__ __align__(16) float g_t2[32 * 18 * 18 * 32];

// --------------------------- main fused kernel ------------------------------
__global__ void __launch_bounds__(576, 1) k_main(
    const float* __restrict__ inp, const float* __restrict__ mat,
    const float* __restrict__ w1_k, const float* __restrict__ w1_b,
    const float* __restrict__ x1_k, const float* __restrict__ x1_b,
    const float* __restrict__ y17_k, const float* __restrict__ y17_b,
    const float* __restrict__ y71_k, const float* __restrict__ y71_b,
    const float* __restrict__ yc_k, const float* __restrict__ yc_b,
    const float* __restrict__ d1_k, const float* __restrict__ d2_k,
    const float* __restrict__ h1_w, const float* __restrict__ h1_b,
    const float* __restrict__ h2_w, const float* __restrict__ h2_b,
    const float* __restrict__ h3_w, const float* __restrict__ h3_b,
    float* __restrict__ out, float* __restrict__ cs_extra) {

    __shared__ __align__(16) float sPart[5832];   // A-partials; prologue scratch
    __shared__ __align__(16) float sP[648];       // P = ghat^T Y, [a*72+j]
    __shared__ __align__(16) float sG12[864];     // ghat rows padded to stride 12
    __shared__ __align__(16) float sGp[720];      // i-pair-packed ghat per grp
    __shared__ __align__(16) float sGT[720];      // ghat^T rows: [b*80 + j]
    __shared__ __align__(16) float sQt[720];      // Q rows stride 80: [a*80+j]
    __shared__ __align__(16) float sR[108];       // [a*12+b]
    __shared__ float sIm[81];
    __shared__ float sLam[1];

    const int tid = threadIdx.x;

    // ======================= w / y / yc branch blocks =======================
    if (blockIdx.x >= 96) {
        float* s_in = sPart;           // 243
        float* s_y1 = sPart + 256;     // 2592
        float* s_y2 = sPart + 2880;    // 2592
        const int b = blockIdx.x - 96;
        for (int k = tid; k < 243; k += 576) s_in[k] = inp[b * 243 + k];
        __syncthreads();

        if (tid < 81) {  // w channel -> out ch 0
            float v = w1_b[0];
            #pragma unroll
            for (int c = 0; c < 3; c++) v += s_in[tid * 3 + c] * w1_k[c];
            out[(b * 81 + tid) * 41] = leakyf(v);
        }
        for (int k = tid; k < 2592; k += 576) {
            int p = k >> 5, o = k & 31;
            int h = p / 9, w = p % 9;
            float v1 = y17_b[o], v2 = y71_b[o];
            #pragma unroll
            for (int kk = 0; kk < 7; kk++) {
                int ww = w + kk - 3;
                if (ww >= 0 && ww < 9) {
                    #pragma unroll
                    for (int c = 0; c < 3; c++)
                        v1 += s_in[(h * 9 + ww) * 3 + c] * y17_k[(kk * 3 + c) * 32 + o];
                }
                int hh = h + kk - 3;
                if (hh >= 0 && hh < 9) {
                    #pragma unroll
                    for (int c = 0; c < 3; c++)
                        v2 += s_in[(hh * 9 + w) * 3 + c] * y71_k[(kk * 3 + c) * 32 + o];
                }
            }
            s_y1[k] = v1;
            s_y2[k] = v2;
        }
        __syncthreads();
        for (int k = tid; k < 2592; k += 576) {
            int p = k >> 5, o = k & 31;
            float v = yc_b[o];
            #pragma unroll 8
            for (int c = 0; c < 32; c++)
                v += s_y1[p * 32 + c] * yc_k[c * 32 + o] + s_y2[p * 32 + c] * yc_k[(32 + c) * 32 + o];
            out[(b * 81 + p) * 41 + 9 + o] = leakyf(v);
        }
        return;
    }

    // ============================ FISTA blocks ==============================
    const int bc = blockIdx.x;
    const int b = bc / 3, c = bc % 3;

    float* s_in  = sPart;          // 243
    float* s_den = sPart + 256;    // 27
    float* sZ1   = sPart + 288;    // 108
    float* sZ2   = sPart + 400;    // 24
    float* sZ3   = sPart + 432;    // 24
    float* sZ4   = sPart + 464;    // 12

    // ghat = sqrt of diagonal entries of mat (mat = kron(ghat, ghat), ghat>=0)
    for (int k = tid; k < 648; k += 576) {
        int i = k / 9, a = k % 9;
        float v = mat[(i * 72 + i) * 81 + (a * 9 + a)];
        sG12[i * 12 + a] = sqrtf(fmaxf(v, 0.f));
    }
    for (int k = tid; k < 243; k += 576) s_in[k] = inp[b * 243 + k];
    for (int k = tid; k < 648; k += 576) sP[k] = 0.f;   // Y=0 -> P=0
    __syncthreads();

    // build packed/transposed G tables + den + d1
    for (int k = tid; k < 360; k += 576) {
        int grp = k / 45, rem = k % 45, k5 = rem / 9, a = rem % 9;
        int i0 = grp * 9 + 2 * k5;
        float v0 = sG12[i0 * 12 + a];
        float v1 = (2 * k5 + 1 < 9) ? sG12[(i0 + 1) * 12 + a] : 0.f;
        sGp[k * 2 + 0] = v0;
        sGp[k * 2 + 1] = v1;
    }
    for (int k = tid; k < 648; k += 576) {
        int jj = k / 9, bb = k % 9;
        sGT[bb * 80 + jj] = sG12[jj * 12 + bb];
    }
    if (tid < 27) {
        float m = 0.f;
        #pragma unroll
        for (int h = 0; h < 9; h++) m = fmaxf(m, fabsf(s_in[h * 27 + tid]));
        s_den[tid] = 0.001f + m;
    }
    if (tid >= 64 && tid < 172) {
        int tt = tid - 64;
        int f = tt % 12, q = tt / 12;
        int oh = q / 3, ow = q % 3;
        float acc = 0.f;
        for (int kh = 0; kh < 5; kh++) {
            int h = oh * 3 - 1 + kh;
            if (h < 0 || h > 8) continue;
            for (int kw = 0; kw < 5; kw++) {
                int w = ow * 3 - 1 + kw;
                if (w < 0 || w > 8) continue;
                #pragma unroll
                for (int cc = 0; cc < 3; cc++)
                    acc += (s_in[(h * 9 + w) * 3 + cc] * BNS) * d1_k[((kh * 5 + kw) * 3 + cc) * 12 + f];
            }
        }
        sZ1[q * 12 + f] = leakyf(acc * BNS);
    }
    __syncthreads();

    if (tid < 81) {
        int w = tid % 9;
        float v = x1_b[c];
        #pragma unroll
        for (int c2 = 0; c2 < 3; c2++)
            v += (s_in[tid * 3 + c2] / s_den[w * 3 + c2]) * x1_k[c2 * 3 + c];
        sIm[tid] = leakyf(v);
    }
    if (tid >= 96 && tid < 120) {
        int f = tid - 96;
        float acc = 0.f;
        for (int kh = 1; kh < 4; kh++)
            for (int kw = 1; kw < 4; kw++)
                #pragma unroll
                for (int cc = 0; cc < 12; cc++)
                    acc += sZ1[((kh - 1) * 3 + (kw - 1)) * 12 + cc] * d2_k[((kh * 5 + kw) * 12 + cc) * 24 + f];
        sZ2[f] = leakyf(acc * BNS);
    }
    __syncthreads();
    if (tid < 24) {
        float v = h1_b[tid];
        #pragma unroll
        for (int f = 0; f < 24; f++) v += sZ2[f] * h1_w[f * 24 + tid];
        sZ3[tid] = v;
    }
    __syncthreads();
    if (tid < 12) {
        float v = h2_b[tid];
        #pragma unroll
        for (int f = 0; f < 24; f++) v += sZ3[f] * h2_w[f * 12 + tid];
        sZ4[tid] = v;
    }
    __syncthreads();
    if (tid == 0) {
        float s = h3_b[0];
        #pragma unroll
        for (int f = 0; f < 12; f++) s += sZ4[f] * h3_w[f];
        sLam[0] = 0.01f / (1.f + expf(-s));   // 0.1*sigmoid * 0.1
    }
    __syncthreads();
    const float lam = sLam[0];

    const int grp = tid / 72;
    const int j   = tid % 72;
    const float* sGpMe = &sGp[grp * 90];

    u64 yv2[5], yl2[5];
    #pragma unroll
    for (int k5 = 0; k5 < 5; k5++) { yv2[k5] = 0ull; yl2[k5] = 0ull; }

    float t = 1.f;
    for (int it = 0; it < 100; it++) {
        // ---- B: R[a][b] = Im[a][b] - sum_j P[a][j] * ghat[j][b]  (f32x2)
        if (tid < 81) {
            int a = tid / 9, bb = tid % 9;
            const float* Pr = &sP[a * 72];
            const float* Gr = &sGT[bb * 80];
            u64 acc0 = 0ull, acc1 = 0ull;
            #pragma unroll
            for (int j2 = 0; j2 < 72; j2 += 4) {
                acc0 = ffma2(*(const u64*)&Pr[j2],     *(const u64*)&Gr[j2],     acc0);
                acc1 = ffma2(*(const u64*)&Pr[j2 + 2], *(const u64*)&Gr[j2 + 2], acc1);
            }
            float x0, x1; upk2(fadd2(acc0, acc1), x0, x1);
            sR[a * 12 + bb] = sIm[tid] - (x0 + x1);
        }
        __syncthreads();
        // ---- C: Qt[a][j2] = sum_b R[a][b] * ghat[j2][b]  (f32x2)
        for (int idx = tid; idx < 648; idx += 576) {
            int a = idx / 72, j2 = idx % 72;
            const float* Rr = &sR[a * 12];
            const float* Gr = &sG12[j2 * 12];
            u64 acc = ffma2(*(const u64*)&Rr[0], *(const u64*)&Gr[0], 0ull);
            acc = ffma2(*(const u64*)&Rr[2], *(const u64*)&Gr[2], acc);
            acc = ffma2(*(const u64*)&Rr[4], *(const u64*)&Gr[4], acc);
            acc = ffma2(*(const u64*)&Rr[6], *(const u64*)&Gr[6], acc);
            float x0, x1; upk2(acc, x0, x1);
            sQt[a * 80 + j2] = x0 + x1 + Rr[8] * Gr[8];
        }
        __syncthreads();
        // ---- D + A fused, f32x2 over i-pairs
        float tn = 0.5f * (1.f + sqrtf(1.f + 4.f * t * t));
        float rmom = (t - 1.f) / tn;
        t = tn;
        u64 q2[9];
        #pragma unroll
        for (int a = 0; a < 9; a++) { float q = sQt[a * 80 + j]; q2[a] = pk2(q, q); }
        u64 acc2[9];
        #pragma unroll
        for (int a = 0; a < 9; a++) acc2[a] = 0ull;
        #pragma unroll
        for (int k5 = 0; k5 < 5; k5++) {
            u64 g2[9];
            #pragma unroll
            for (int a = 0; a < 9; a++) g2[a] = *(const u64*)&sGpMe[(k5 * 9 + a) * 2];
            u64 wv2 = yv2[k5];
            #pragma unroll
            for (int a = 0; a < 9; a++) wv2 = ffma2(g2[a], q2[a], wv2);
            float w0, w1; upk2(wv2, w0, w1);
            float yn0 = fmaxf(w0 - lam, 0.f) - fmaxf(-w0 - lam, 0.f);
            float yn1 = fmaxf(w1 - lam, 0.f) - fmaxf(-w1 - lam, 0.f);
            float p0, p1; upk2(yl2[k5], p0, p1);
            float yx0 = yn0 + rmom * (yn0 - p0);
            float yx1 = yn1 + rmom * (yn1 - p1);
            yl2[k5] = pk2(yn0, yn1);
            u64 yx2 = pk2(yx0, yx1);
            yv2[k5] = yx2;
            #pragma unroll
            for (int a = 0; a < 9; a++) acc2[a] = ffma2(g2[a], yx2, acc2[a]);
        }
        #pragma unroll
        for (int a = 0; a < 9; a++) {
            float x0, x1; upk2(acc2[a], x0, x1);
            sPart[(a * 72 + j) * 9 + grp] = x0 + x1;
        }
        __syncthreads();
        // ---- reduce partials -> sP
        for (int idx = tid; idx < 648; idx += 576) {
            const float* pp = &sPart[idx * 9];
            sP[idx] = ((pp[0] + pp[1]) + (pp[2] + pp[3]))
                    + ((pp[4] + pp[5]) + (pp[6] + pp[7]));
        }
        __syncthreads();
    }

    // cs_out[b,i,j,c] = y_new (yl holds ynew of last iteration)
    #pragma unroll
    for (int k5 = 0; k5 < 5; k5++) {
        float a0, a1; upk2(yl2[k5], a0, a1);
        int i0 = grp * 9 + 2 * k5;
        int k = i0 * 72 + j;
        g_cs[(b * 5184 + k) * 3 + c] = a0;
        if (cs_extra) cs_extra[(b * 5184 + k) * 3 + c] = a0;
        if (2 * k5 + 1 < 9) {
            int k1 = (i0 + 1) * 72 + j;
            g_cs[(b * 5184 + k1) * 3 + c] = a1;
            if (cs_extra) cs_extra[(b * 5184 + k1) * 3 + c] = a1;
        }
    }
}

// --------------------------- post-FISTA conv chain --------------------------
// c51: (5,1,3,16) stride 2, 72->36; H pad lo=1. Thread owns 4 o's (float4 w).
__global__ void __launch_bounds__(256) k_c51(const float* __restrict__ k51,
                                             const float* __restrict__ b51) {
    int idx = blockIdx.x * 256 + threadIdx.x;      // 648 blocks: 32*36*36*4
    int o4 = idx & 3;
    int ow = (idx >> 2) % 36;
    int oh = ((idx >> 2) / 36) % 36;
    int b = idx / (4 * 1296);
    int w = 2 * ow;
    float4 v = *(const float4*)&b51[o4 * 4];
    #pragma unroll
    for (int kh = 0; kh < 5; kh++) {
        int h = 2 * oh - 1 + kh;
        if (h < 0 || h > 71) continue;
        const float* src = g_cs + ((b * 72 + h) * 72 + w) * 3;
        #pragma unroll
        for (int c = 0; c < 3; c++) {
            float s = src[c];
            float4 w4 = *(const float4*)&k51[(kh * 3 + c) * 16 + o4 * 4];
            v.x += s * w4.x; v.y += s * w4.y; v.z += s * w4.z; v.w += s * w4.w;
        }
    }
    *(float4*)&g_t1[((b * 36 + oh) * 36 + ow) * 16 + o4 * 4] = v;
}

// c15: (1,5,16,32) stride 2, 36->18; W pad lo=1. Thread owns 4 o's.
__global__ void __launch_bounds__(256) k_c15(const float* __restrict__ k15,
                                             const float* __restrict__ b15) {
    int idx = blockIdx.x * 256 + threadIdx.x;      // 324 blocks: 32*18*18*8
    int o4 = idx & 7;
    int ow = (idx >> 3) % 18;
    int oh = ((idx >> 3) / 18) % 18;
    int b = idx / (8 * 324);
    int h = 2 * oh;
    float4 v = *(const float4*)&b15[o4 * 4];
    #pragma unroll
    for (int kw = 0; kw < 5; kw++) {
        int w = 2 * ow - 1 + kw;
        if (w < 0 || w > 35) continue;
        const float* src = g_t1 + ((b * 36 + h) * 36 + w) * 16;
        #pragma unroll
        for (int c4 = 0; c4 < 4; c4++) {
            float4 s4 = *(const float4*)&src[c4 * 4];
            #pragma unroll
            for (int cc = 0; cc < 4; cc++) {
                int cidx = c4 * 4 + cc;
                float s = (cc == 0) ? s4.x : (cc == 1) ? s4.y : (cc == 2) ? s4.z : s4.w;
                float4 w4 = *(const float4*)&k15[(kw * 16 + cidx) * 32 + o4 * 4];
                v.x += s * w4.x; v.y += s * w4.y; v.z += s * w4.z; v.w += s * w4.w;
            }
        }
    }
    *(float4*)&g_t2[((b * 18 + oh) * 18 + ow) * 32 + o4 * 4] = v;
}

// c55 (5,5,32,64) s2 + x2 (1x1 64->8 leaky). Thread owns 4 o's (float4).
__global__ void __launch_bounds__(256) k_c55x2(const float* __restrict__ k55,
                                               const float* __restrict__ b55,
                                               const float* __restrict__ kx2,
                                               const float* __restrict__ bx2,
                                               float* __restrict__ out) {
    __shared__ float sv[16][68];
    const int t = threadIdx.x;                    // 162 blocks: 32*81*16
    const int o4 = t & 15;
    const int pslot = t >> 4;
    const int plin = blockIdx.x * 16 + pslot;     // b*81 + p
    const int ow = plin % 9;
    const int oh = (plin / 9) % 9;
    const int b = plin / 81;
    float4 v = *(const float4*)&b55[o4 * 4];
    for (int kh = 0; kh < 5; kh++) {
        int h = 2 * oh - 1 + kh;
        if (h < 0 || h > 17) continue;
        for (int kw = 0; kw < 5; kw++) {
            int w = 2 * ow - 1 + kw;
            if (w < 0 || w > 17) continue;
            const float* src = g_t2 + ((b * 18 + h) * 18 + w) * 32;
            const float* wk = k55 + ((kh * 5 + kw) * 32) * 64 + o4 * 4;
            #pragma unroll
            for (int c4 = 0; c4 < 8; c4++) {
                float4 s4 = *(const float4*)&src[c4 * 4];
                float4 w0 = *(const float4*)&wk[(c4 * 4 + 0) * 64];
                float4 w1 = *(const float4*)&wk[(c4 * 4 + 1) * 64];
                float4 w2 = *(const float4*)&wk[(c4 * 4 + 2) * 64];
                float4 w3 = *(const float4*)&wk[(c4 * 4 + 3) * 64];
                v.x += s4.x * w0.x + s4.y * w1.x + s4.z * w2.x + s4.w * w3.x;
                v.y += s4.x * w0.y + s4.y * w1.y + s4.z * w2.y + s4.w * w3.y;
                v.z += s4.x * w0.z + s4.y * w1.z + s4.z * w2.z + s4.w * w3.z;
                v.w += s4.x * w0.w + s4.y * w1.w + s4.z * w2.w + s4.w * w3.w;
            }
        }
    }
    *(float4*)&sv[pslot][o4 * 4] = v;
    __syncthreads();
    if (t < 128) {
        int pix = t >> 3, o2 = t & 7;
        float v2 = bx2[o2];
        #pragma unroll 8
        for (int c = 0; c < 64; c++)
            v2 += sv[pix][c] * kx2[c * 8 + o2];
        out[(blockIdx.x * 16 + pix) * 41 + 1 + o2] = leakyf(v2);
    }
}

// ---------------------------------------------------------------------------
extern "C" void kernel_launch(void* const* d_in, const int* in_sizes, int n_in,
                              void* d_out, int out_size) {
    const float* inp  = (const float*)d_in[0];
    const float* mat  = (const float*)d_in[1];
    const float* w1_k = (const float*)d_in[2];
    const float* w1_b = (const float*)d_in[3];
    const float* x1_k = (const float*)d_in[4];
    const float* x1_b = (const float*)d_in[5];
    const float* c51_k = (const float*)d_in[6];
    const float* c51_b = (const float*)d_in[7];
    const float* c15_k = (const float*)d_in[8];
    const float* c15_b = (const float*)d_in[9];
    const float* c55_k = (const float*)d_in[10];
    const float* c55_b = (const float*)d_in[11];
    const float* x2_k = (const float*)d_in[12];
    const float* x2_b = (const float*)d_in[13];
    const float* y17_k = (const float*)d_in[14];
    const float* y17_b = (const float*)d_in[15];
    const float* y71_k = (const float*)d_in[16];
    const float* y71_b = (const float*)d_in[17];
    const float* yc_k = (const float*)d_in[18];
    const float* yc_b = (const float*)d_in[19];
    const float* d1_k = (const float*)d_in[20];
    const float* d2_k = (const float*)d_in[21];
    const float* h1_w = (const float*)d_in[22];
    const float* h1_b = (const float*)d_in[23];
    const float* h2_w = (const float*)d_in[24];
    const float* h2_b = (const float*)d_in[25];
    const float* h3_w = (const float*)d_in[26];
    const float* h3_b = (const float*)d_in[27];

    float* out = (float*)d_out;
    const int OUT1 = 32 * 9 * 9 * 41;              // 106272
    const int OUT2 = 32 * 72 * 72 * 3;             // 497664
    float* cs_extra = (out_size >= OUT1 + OUT2) ? (out + OUT1) : nullptr;

    k_main<<<128, 576>>>(inp, mat, w1_k, w1_b, x1_k, x1_b, y17_k, y17_b,
                         y71_k, y71_b, yc_k, yc_b, d1_k, d2_k,
                         h1_w, h1_b, h2_w, h2_b, h3_w, h3_b, out, cs_extra);
    k_c51<<<648, 256>>>(c51_k, c51_b);
    k_c15<<<324, 256>>>(c15_k, c15_b);
    k_c55x2<<<162, 256>>>(c55_k, c55_b, x2_k, x2_b, out);
}